// round 15
// baseline (speedup 1.0000x reference)
#include <cuda_runtime.h>
#include <cuda_bf16.h>
#include <math.h>
#include <stdint.h>

#define B_ 8
#define N_ 1024
#define C_ 512
#define H_ 8
#define D_ 64
#define S2_ 1024   // 2*SPAN

#define INV_SCALE 0.07216878364870323f   // 1/sqrt(64*3)

// ---------------- scratch (static device arrays; no allocation) -------------
__device__ float g_Q[(size_t)B_ * N_ * C_];
__device__ float g_K[(size_t)B_ * N_ * C_];
__device__ float g_V[(size_t)B_ * N_ * C_];
__device__ float g_posK[(size_t)S2_ * C_];
__device__ float g_posQ[(size_t)S2_ * C_];
__device__ __nv_bfloat16 g_S2[(size_t)B_ * H_ * N_ * S2_];   // prescaled, bf16
__device__ __nv_bfloat16 g_S3[(size_t)B_ * H_ * N_ * S2_];   // prescaled, bf16

// ---------------- tf32 mma helpers ------------------------------------------
__device__ __forceinline__ uint32_t f2tf32(float x) {
    uint32_t r;
    asm("cvt.rna.tf32.f32 %0, %1;" : "=r"(r) : "f"(x));
    return r;
}

__device__ __forceinline__ void mma_tf32(
    float c[4], uint32_t a0, uint32_t a1, uint32_t a2, uint32_t a3,
    uint32_t b0, uint32_t b1)
{
    asm volatile(
        "mma.sync.aligned.m16n8k8.row.col.f32.tf32.tf32.f32 "
        "{%0,%1,%2,%3}, {%4,%5,%6,%7}, {%8,%9}, {%0,%1,%2,%3};"
        : "+f"(c[0]), "+f"(c[1]), "+f"(c[2]), "+f"(c[3])
        : "r"(a0), "r"(a1), "r"(a2), "r"(a3), "r"(b0), "r"(b1));
}

__device__ __forceinline__ void ldsm_x4(
    uint32_t& r0, uint32_t& r1, uint32_t& r2, uint32_t& r3, uint32_t addr)
{
    asm volatile(
        "ldmatrix.sync.aligned.m8n8.x4.shared.b16 {%0,%1,%2,%3}, [%4];"
        : "=r"(r0), "=r"(r1), "=r"(r2), "=r"(r3) : "r"(addr));
}

// ============================================================================
// Merged projections (tf32 mma): Y[M,512] = X[M,512] @ W[512,512] + b
// ============================================================================
#define PA_STRIDE 36
#define PB_STRIDE 132
__global__ __launch_bounds__(256) void proj_all(
    const float* __restrict__ q, const float* __restrict__ k,
    const float* __restrict__ val, const float* __restrict__ rel,
    const float* __restrict__ Wq, const float* __restrict__ bq,
    const float* __restrict__ Wk, const float* __restrict__ bk,
    const float* __restrict__ Wv, const float* __restrict__ bv,
    float* __restrict__ pQ, float* __restrict__ pK, float* __restrict__ pV,
    float* __restrict__ pPK, float* __restrict__ pPQ)
{
    __shared__ uint32_t As[128][PA_STRIDE];
    __shared__ uint32_t Bs[32][PB_STRIDE];

    const int tid = threadIdx.x;
    const int warp = tid >> 5, lane = tid & 31;
    const int g = lane >> 2, t = lane & 3;
    const int wm = (warp & 1) << 6;
    const int wn = (warp >> 1) << 5;

    const int gy = blockIdx.y;
    const float *X, *W, *bias;
    float* Y;
    int mb;
    if (gy < 64)       { X = q;   W = Wq; bias = bq; Y = pQ;  mb = gy; }
    else if (gy < 128) { X = k;   W = Wk; bias = bk; Y = pK;  mb = gy - 64; }
    else if (gy < 192) { X = val; W = Wv; bias = bv; Y = pV;  mb = gy - 128; }
    else if (gy < 200) { X = rel; W = Wk; bias = bk; Y = pPK; mb = gy - 192; }
    else               { X = rel; W = Wq; bias = bq; Y = pPQ; mb = gy - 200; }

    const int m0 = mb << 7, n0 = blockIdx.x << 7;

    int arow[4], acol[4], brow[4], bcol[4];
#pragma unroll
    for (int i = 0; i < 4; i++) {
        int idx = (i << 8) + tid;
        arow[i] = idx >> 3;  acol[i] = (idx & 7) << 2;
        brow[i] = idx >> 5;  bcol[i] = (idx & 31) << 2;
    }

    float c[4][4][4];
#pragma unroll
    for (int mt = 0; mt < 4; mt++)
#pragma unroll
        for (int nt = 0; nt < 4; nt++)
#pragma unroll
            for (int e = 0; e < 4; e++) c[mt][nt][e] = 0.f;

    float4 xa[4], xb[4];
#pragma unroll
    for (int i = 0; i < 4; i++) {
        xa[i] = *(const float4*)&X[(size_t)(m0 + arow[i]) * 512 + acol[i]];
        xb[i] = *(const float4*)&W[(size_t)brow[i] * 512 + n0 + bcol[i]];
    }

    for (int k0 = 0; k0 < 512; k0 += 32) {
#pragma unroll
        for (int i = 0; i < 4; i++) {
            *(uint4*)&As[arow[i]][acol[i]] = make_uint4(
                f2tf32(xa[i].x), f2tf32(xa[i].y), f2tf32(xa[i].z), f2tf32(xa[i].w));
            *(uint4*)&Bs[brow[i]][bcol[i]] = make_uint4(
                f2tf32(xb[i].x), f2tf32(xb[i].y), f2tf32(xb[i].z), f2tf32(xb[i].w));
        }
        __syncthreads();

        if (k0 + 32 < 512) {
#pragma unroll
            for (int i = 0; i < 4; i++) {
                xa[i] = *(const float4*)&X[(size_t)(m0 + arow[i]) * 512 + k0 + 32 + acol[i]];
                xb[i] = *(const float4*)&W[(size_t)(k0 + 32 + brow[i]) * 512 + n0 + bcol[i]];
            }
        }

#pragma unroll
        for (int k8 = 0; k8 < 32; k8 += 8) {
            uint32_t a[4][4], b[4][2];
#pragma unroll
            for (int mt = 0; mt < 4; mt++) {
                int rb = wm + (mt << 4);
                a[mt][0] = As[rb + g][k8 + t];
                a[mt][1] = As[rb + g + 8][k8 + t];
                a[mt][2] = As[rb + g][k8 + t + 4];
                a[mt][3] = As[rb + g + 8][k8 + t + 4];
            }
#pragma unroll
            for (int nt = 0; nt < 4; nt++) {
                int nb = wn + (nt << 3) + g;
                b[nt][0] = Bs[k8 + t][nb];
                b[nt][1] = Bs[k8 + t + 4][nb];
            }
#pragma unroll
            for (int mt = 0; mt < 4; mt++)
#pragma unroll
                for (int nt = 0; nt < 4; nt++)
                    mma_tf32(c[mt][nt], a[mt][0], a[mt][1], a[mt][2], a[mt][3],
                             b[nt][0], b[nt][1]);
        }
        __syncthreads();
    }

#pragma unroll
    for (int mt = 0; mt < 4; mt++) {
        int r0 = m0 + wm + (mt << 4) + g;
#pragma unroll
        for (int nt = 0; nt < 4; nt++) {
            int cb = n0 + wn + (nt << 3) + (t << 1);
            float b0v = bias[cb], b1v = bias[cb + 1];
            *(float2*)&Y[(size_t)r0 * 512 + cb] =
                make_float2(c[mt][nt][0] + b0v, c[mt][nt][1] + b1v);
            *(float2*)&Y[(size_t)(r0 + 8) * 512 + cb] =
                make_float2(c[mt][nt][2] + b0v, c[mt][nt][3] + b1v);
        }
    }
}

// ============================================================================
// S2/S3 (tf32 mma), banded, bf16 output (prescaled).
// ============================================================================
#define POS_STRIDE 68
__global__ __launch_bounds__(256) void pos_kernel(
    const float* __restrict__ Q, const float* __restrict__ K,
    const float* __restrict__ posK, const float* __restrict__ posQ,
    __nv_bfloat16* __restrict__ S2, __nv_bfloat16* __restrict__ S3)
{
    const int by = blockIdx.y, bx = blockIdx.x;
    const int z = blockIdx.z;
    const bool isS3 = z >= 64;
    if (!isS3) {
        if (bx > by + 4 || by > bx + 4) return;
    } else {
        int s = bx + by;
        if (s < 3 || s > 11) return;
    }

    extern __shared__ uint32_t psm[];
    uint32_t (*As)[POS_STRIDE] = (uint32_t(*)[POS_STRIDE])psm;
    uint32_t (*Ps)[POS_STRIDE] = (uint32_t(*)[POS_STRIDE])(psm + 128 * POS_STRIDE);

    const int zz = isS3 ? z - 64 : z;
    const int b = zz >> 3, h = zz & 7;
    const int m0 = by << 7, n0 = bx << 7;
    const int tid = threadIdx.x;
    const int warp = tid >> 5, lane = tid & 31;
    const int g = lane >> 2, t = lane & 3;
    const int wm = (warp & 1) << 6;
    const int wn = (warp >> 1) << 5;

    const float* A = (isS3 ? K : Q) + ((size_t)(b * N_ + m0)) * C_ + h * D_;
    const float* P = (isS3 ? posQ : posK) + (size_t)n0 * C_ + h * D_;
    __nv_bfloat16* OUT = (isS3 ? S3 : S2) + (size_t)zz * N_ * S2_;

#pragma unroll
    for (int i = 0; i < 8; i++) {
        int idx = (i << 8) + tid;
        int row = idx >> 4, cc = (idx & 15) << 2;
        float4 va = *(const float4*)&A[(size_t)row * C_ + cc];
        *(uint4*)&As[row][cc] = make_uint4(f2tf32(va.x), f2tf32(va.y),
                                           f2tf32(va.z), f2tf32(va.w));
        float4 vp = *(const float4*)&P[(size_t)row * C_ + cc];
        *(uint4*)&Ps[row][cc] = make_uint4(f2tf32(vp.x), f2tf32(vp.y),
                                           f2tf32(vp.z), f2tf32(vp.w));
    }
    __syncthreads();

    float c[4][4][4];
#pragma unroll
    for (int mt = 0; mt < 4; mt++)
#pragma unroll
        for (int nt = 0; nt < 4; nt++)
#pragma unroll
            for (int e = 0; e < 4; e++) c[mt][nt][e] = 0.f;

#pragma unroll
    for (int k8 = 0; k8 < 64; k8 += 8) {
        uint32_t a[4][4], bfr[4][2];
#pragma unroll
        for (int mt = 0; mt < 4; mt++) {
            int rb = wm + (mt << 4);
            a[mt][0] = As[rb + g][k8 + t];
            a[mt][1] = As[rb + g + 8][k8 + t];
            a[mt][2] = As[rb + g][k8 + t + 4];
            a[mt][3] = As[rb + g + 8][k8 + t + 4];
        }
#pragma unroll
        for (int nt = 0; nt < 4; nt++) {
            int nb = wn + (nt << 3) + g;
            bfr[nt][0] = Ps[nb][k8 + t];
            bfr[nt][1] = Ps[nb][k8 + t + 4];
        }
#pragma unroll
        for (int mt = 0; mt < 4; mt++)
#pragma unroll
            for (int nt = 0; nt < 4; nt++)
                mma_tf32(c[mt][nt], a[mt][0], a[mt][1], a[mt][2], a[mt][3],
                         bfr[nt][0], bfr[nt][1]);
    }

#pragma unroll
    for (int mt = 0; mt < 4; mt++) {
        int r0 = m0 + wm + (mt << 4) + g;
#pragma unroll
        for (int nt = 0; nt < 4; nt++) {
            int cb = n0 + wn + (nt << 3) + (t << 1);
            *(__nv_bfloat162*)&OUT[(size_t)r0 * S2_ + cb] =
                __floats2bfloat162_rn(c[mt][nt][0] * INV_SCALE,
                                      c[mt][nt][1] * INV_SCALE);
            *(__nv_bfloat162*)&OUT[(size_t)(r0 + 8) * S2_ + cb] =
                __floats2bfloat162_rn(c[mt][nt][2] * INV_SCALE,
                                      c[mt][nt][3] * INV_SCALE);
        }
    }
}

// ============================================================================
// Tensor-core fused attention — round-14 structure (256-row CTA, 32-row warp
// tiles), fragment loads via ldmatrix.x4 for Qs-A, Ks-B, Ps-A (values and
// arithmetic bit-identical; ~2x fewer smem instructions in hot loops).
// ============================================================================
#define AQ_STR 68
#define AV_STR 72
#define ATTN_SMEM ((256*AQ_STR + 64*AQ_STR + 64*AV_STR + 256*AQ_STR) * 4)
__global__ __launch_bounds__(256) void attn_tc(
    const float* __restrict__ Q, const float* __restrict__ K,
    const float* __restrict__ V, const __nv_bfloat16* __restrict__ S2,
    const __nv_bfloat16* __restrict__ S3, float* __restrict__ OUT)
{
    extern __shared__ uint32_t asmem[];
    uint32_t (*Qs)[AQ_STR] = (uint32_t(*)[AQ_STR])asmem;                      // [256][68]
    uint32_t (*Ks)[AQ_STR] = (uint32_t(*)[AQ_STR])(asmem + 256 * AQ_STR);     // [64][68]
    uint32_t (*Vs)[AV_STR] = (uint32_t(*)[AV_STR])(asmem + 320 * AQ_STR);     // [64][72]
    uint32_t (*Ps)[AQ_STR] = (uint32_t(*)[AQ_STR])(asmem + 320 * AQ_STR + 64 * AV_STR); // [256][68]

    const int z = blockIdx.y, b = z >> 3, h = z & 7;
    const int q0 = blockIdx.x << 8;           // 256-row q tile
    const int tid = threadIdx.x;
    const int warp = tid >> 5, lane = tid & 31;
    const int g = lane >> 2, t = lane & 3;
    const int lr = lane & 7, sub = lane >> 3;

    // Load Q tile (256x64), prescale, tf32 into Qs
#pragma unroll
    for (int i = 0; i < 16; i++) {
        int idx = (i << 8) + tid;
        int row = idx >> 4, cc = (idx & 15) << 2;
        float4 v = *(const float4*)&Q[((size_t)(b * N_ + q0 + row)) * C_ + h * D_ + cc];
        *(uint4*)&Qs[row][cc] = make_uint4(
            f2tf32(v.x * INV_SCALE), f2tf32(v.y * INV_SCALE),
            f2tf32(v.z * INV_SCALE), f2tf32(v.w * INV_SCALE));
    }

    const int qrl = (warp << 5) + g;          // local q row of fragment 0
    const int qg0 = q0 + qrl;                 // rows qg0, +8, +16, +24
    const __nv_bfloat16* s2r0 = S2 + ((size_t)z * N_ + qg0) * S2_;
    const __nv_bfloat16* s2r1 = s2r0 + (size_t)8  * S2_;
    const __nv_bfloat16* s2r2 = s2r0 + (size_t)16 * S2_;
    const __nv_bfloat16* s2r3 = s2r0 + (size_t)24 * S2_;
    const __nv_bfloat16* S3z = S3 + (size_t)z * N_ * S2_;

    // ---- ldmatrix per-lane base addresses (byte units) ----
    // A-pattern at (row_base, k8): mat0 rows rb+0..7 col k8; mat1 rows rb+8..15
    // col k8; mat2 rows rb+0..7 col k8+4; mat3 rows rb+8..15 col k8+4.
    const uint32_t aoff = ((((sub & 1) << 3) + lr) * AQ_STR + ((sub >> 1) << 2)) << 2;
    // B-pattern (Ks) for nt pair: row = (ntp*16) + (sub>>1)*8 + lr, col = k8 + (sub&1)*4
    const uint32_t boff = ((((sub >> 1) << 3) + lr) * AQ_STR + ((sub & 1) << 2)) << 2;

    const uint32_t qsBase = (uint32_t)__cvta_generic_to_shared(Qs);
    const uint32_t ksBase = (uint32_t)__cvta_generic_to_shared(Ks);
    const uint32_t psBase = (uint32_t)__cvta_generic_to_shared(Ps);
    const uint32_t qA0 = qsBase + ((uint32_t)(warp << 5) * AQ_STR << 2) + aoff;
    const uint32_t qA1 = qA0 + (16 * AQ_STR << 2);
    const uint32_t pA0 = psBase + ((uint32_t)(warp << 5) * AQ_STR << 2) + aoff;
    const uint32_t pA1 = pA0 + (16 * AQ_STR << 2);
    const uint32_t kB0 = ksBase + boff;

    float o[2][8][4];
#pragma unroll
    for (int mf = 0; mf < 2; mf++)
#pragma unroll
        for (int nt = 0; nt < 8; nt++)
#pragma unroll
            for (int e = 0; e < 4; e++) o[mf][nt][e] = 0.f;
    float mr[4] = {-1e30f, -1e30f, -1e30f, -1e30f};
    float lr_[4] = {0.f, 0.f, 0.f, 0.f};

    for (int k0 = 0; k0 < N_; k0 += 64) {
        // ---- load K,V tiles (64x64 each), 4 float4 per thread ----
#pragma unroll
        for (int i = 0; i < 4; i++) {
            int idx = (i << 8) + tid;
            int row = idx >> 4, cc = (idx & 15) << 2;
            float4 kv = *(const float4*)&K[((size_t)(b * N_ + k0 + row)) * C_ + h * D_ + cc];
            *(uint4*)&Ks[row][cc] = make_uint4(f2tf32(kv.x), f2tf32(kv.y),
                                               f2tf32(kv.z), f2tf32(kv.w));
            float4 vv = *(const float4*)&V[((size_t)(b * N_ + k0 + row)) * C_ + h * D_ + cc];
            *(uint4*)&Vs[row][cc] = make_uint4(f2tf32(vv.x), f2tf32(vv.y),
                                               f2tf32(vv.z), f2tf32(vv.w));
        }
        __syncthreads();

        // ---- QK: warp computes 32 x 64 scores (2 m16 fragments) ----
        float cf[2][8][4];
#pragma unroll
        for (int mf = 0; mf < 2; mf++)
#pragma unroll
            for (int nt = 0; nt < 8; nt++)
#pragma unroll
                for (int e = 0; e < 4; e++) cf[mf][nt][e] = 0.f;
#pragma unroll
        for (int k8 = 0; k8 < 64; k8 += 8) {
            uint32_t a00, a01, a02, a03, a10, a11, a12, a13;
            ldsm_x4(a00, a01, a02, a03, qA0 + (k8 << 2));
            ldsm_x4(a10, a11, a12, a13, qA1 + (k8 << 2));
#pragma unroll
            for (int ntp = 0; ntp < 4; ntp++) {
                uint32_t b0a, b1a, b0b, b1b;
                ldsm_x4(b0a, b1a, b0b, b1b,
                        kB0 + ((uint32_t)ntp * 16 * AQ_STR << 2) + (k8 << 2));
                mma_tf32(cf[0][2 * ntp],     a00, a01, a02, a03, b0a, b1a);
                mma_tf32(cf[1][2 * ntp],     a10, a11, a12, a13, b0a, b1a);
                mma_tf32(cf[0][2 * ntp + 1], a00, a01, a02, a03, b0b, b1b);
                mma_tf32(cf[1][2 * ntp + 1], a10, a11, a12, a13, b0b, b1b);
            }
        }

        // ---- add position terms (bf16 gathers, index clip(q-k+512)) ----
#pragma unroll
        for (int nt = 0; nt < 8; nt++) {
            int kj = k0 + (nt << 3) + (t << 1);
            const __nv_bfloat16* s3c0 = S3z + (size_t)kj * S2_;
            const __nv_bfloat16* s3c1 = s3c0 + S2_;
            int d00 = qg0 - kj + 512;
            int c00 = min(max(d00, 0), 1023);
            int c01 = min(max(d00 - 1, 0), 1023);
            int c10 = min(max(d00 + 8, 0), 1023);
            int c11 = min(max(d00 + 7, 0), 1023);
            int c20 = min(max(d00 + 16, 0), 1023);
            int c21 = min(max(d00 + 15, 0), 1023);
            int c30 = min(max(d00 + 24, 0), 1023);
            int c31 = min(max(d00 + 23, 0), 1023);
            cf[0][nt][0] += __bfloat162float(s2r0[c00]) + __bfloat162float(s3c0[c00]);
            cf[0][nt][1] += __bfloat162float(s2r0[c01]) + __bfloat162float(s3c1[c01]);
            cf[0][nt][2] += __bfloat162float(s2r1[c10]) + __bfloat162float(s3c0[c10]);
            cf[0][nt][3] += __bfloat162float(s2r1[c11]) + __bfloat162float(s3c1[c11]);
            cf[1][nt][0] += __bfloat162float(s2r2[c20]) + __bfloat162float(s3c0[c20]);
            cf[1][nt][1] += __bfloat162float(s2r2[c21]) + __bfloat162float(s3c1[c21]);
            cf[1][nt][2] += __bfloat162float(s2r3[c30]) + __bfloat162float(s3c0[c30]);
            cf[1][nt][3] += __bfloat162float(s2r3[c31]) + __bfloat162float(s3c1[c31]);
        }

        // ---- online softmax for 4 owned rows (quad reduce over t) ----
        float tm[4] = {-1e30f, -1e30f, -1e30f, -1e30f};
#pragma unroll
        for (int nt = 0; nt < 8; nt++) {
            tm[0] = fmaxf(tm[0], fmaxf(cf[0][nt][0], cf[0][nt][1]));
            tm[1] = fmaxf(tm[1], fmaxf(cf[0][nt][2], cf[0][nt][3]));
            tm[2] = fmaxf(tm[2], fmaxf(cf[1][nt][0], cf[1][nt][1]));
            tm[3] = fmaxf(tm[3], fmaxf(cf[1][nt][2], cf[1][nt][3]));
        }
        float al[4];
#pragma unroll
        for (int r = 0; r < 4; r++) {
            tm[r] = fmaxf(tm[r], __shfl_xor_sync(0xffffffffu, tm[r], 1));
            tm[r] = fmaxf(tm[r], __shfl_xor_sync(0xffffffffu, tm[r], 2));
            float nm = fmaxf(mr[r], tm[r]);
            al[r] = __expf(mr[r] - nm);
            mr[r] = nm;
        }

        float rs[4] = {0.f, 0.f, 0.f, 0.f};
#pragma unroll
        for (int nt = 0; nt < 8; nt++) {
            cf[0][nt][0] = __expf(cf[0][nt][0] - mr[0]); rs[0] += cf[0][nt][0];
            cf[0][nt][1] = __expf(cf[0][nt][1] - mr[0]); rs[0] += cf[0][nt][1];
            cf[0][nt][2] = __expf(cf[0][nt][2] - mr[1]); rs[1] += cf[0][nt][2];
            cf[0][nt][3] = __expf(cf[0][nt][3] - mr[1]); rs[1] += cf[0][nt][3];
            cf[1][nt][0] = __expf(cf[1][nt][0] - mr[2]); rs[2] += cf[1][nt][0];
            cf[1][nt][1] = __expf(cf[1][nt][1] - mr[2]); rs[2] += cf[1][nt][1];
            cf[1][nt][2] = __expf(cf[1][nt][2] - mr[3]); rs[3] += cf[1][nt][2];
            cf[1][nt][3] = __expf(cf[1][nt][3] - mr[3]); rs[3] += cf[1][nt][3];
        }
#pragma unroll
        for (int r = 0; r < 4; r++) {
            rs[r] += __shfl_xor_sync(0xffffffffu, rs[r], 1);
            rs[r] += __shfl_xor_sync(0xffffffffu, rs[r], 2);
            lr_[r] = lr_[r] * al[r] + rs[r];
        }
#pragma unroll
        for (int nt = 0; nt < 8; nt++) {
            o[0][nt][0] *= al[0]; o[0][nt][1] *= al[0];
            o[0][nt][2] *= al[1]; o[0][nt][3] *= al[1];
            o[1][nt][0] *= al[2]; o[1][nt][1] *= al[2];
            o[1][nt][2] *= al[3]; o[1][nt][3] *= al[3];
        }

        // ---- P -> smem (tf32); warp-local rows, warp-sync only ----
#pragma unroll
        for (int nt = 0; nt < 8; nt++) {
            int col = (nt << 3) + (t << 1);
            *(uint2*)&Ps[qrl][col]      = make_uint2(f2tf32(cf[0][nt][0]), f2tf32(cf[0][nt][1]));
            *(uint2*)&Ps[qrl + 8][col]  = make_uint2(f2tf32(cf[0][nt][2]), f2tf32(cf[0][nt][3]));
            *(uint2*)&Ps[qrl + 16][col] = make_uint2(f2tf32(cf[1][nt][0]), f2tf32(cf[1][nt][1]));
            *(uint2*)&Ps[qrl + 24][col] = make_uint2(f2tf32(cf[1][nt][2]), f2tf32(cf[1][nt][3]));
        }
        __syncwarp();

        // ---- o += P · V ----
#pragma unroll
        for (int k8 = 0; k8 < 64; k8 += 8) {
            uint32_t a00, a01, a02, a03, a10, a11, a12, a13;
            ldsm_x4(a00, a01, a02, a03, pA0 + (k8 << 2));
            ldsm_x4(a10, a11, a12, a13, pA1 + (k8 << 2));
#pragma unroll
            for (int nt = 0; nt < 8; nt++) {
                uint32_t b0 = Vs[k8 + t][(nt << 3) + g];
                uint32_t b1 = Vs[k8 + t + 4][(nt << 3) + g];
                mma_tf32(o[0][nt], a00, a01, a02, a03, b0, b1);
                mma_tf32(o[1][nt], a10, a11, a12, a13, b0, b1);
            }
        }
        __syncthreads();   // Ks/Vs consumed; next iteration overwrites
    }

    // ---- epilogue: 4 owned rows ----
    float inv[4];
#pragma unroll
    for (int r = 0; r < 4; r++) inv[r] = 1.f / lr_[r];
#pragma unroll
    for (int nt = 0; nt < 8; nt++) {
        int col = h * D_ + (nt << 3) + (t << 1);
        *(float2*)&OUT[((size_t)(b * N_ + qg0)) * C_ + col] =
            make_float2(o[0][nt][0] * inv[0], o[0][nt][1] * inv[0]);
        *(float2*)&OUT[((size_t)(b * N_ + qg0 + 8)) * C_ + col] =
            make_float2(o[0][nt][2] * inv[1], o[0][nt][3] * inv[1]);
        *(float2*)&OUT[((size_t)(b * N_ + qg0 + 16)) * C_ + col] =
            make_float2(o[1][nt][0] * inv[2], o[1][nt][1] * inv[2]);
        *(float2*)&OUT[((size_t)(b * N_ + qg0 + 24)) * C_ + col] =
            make_float2(o[1][nt][2] * inv[3], o[1][nt][3] * inv[3]);
    }
}

// ---------------------------------------------------------------------------
extern "C" void kernel_launch(void* const* d_in, const int* in_sizes, int n_in,
                              void* d_out, int out_size)
{
    const float* q   = (const float*)d_in[0];
    const float* k   = (const float*)d_in[1];
    const float* val = (const float*)d_in[2];
    const float* rel = (const float*)d_in[3];
    const float* Wq  = (const float*)d_in[4];
    const float* bq  = (const float*)d_in[5];
    const float* Wk  = (const float*)d_in[6];
    const float* bk  = (const float*)d_in[7];
    const float* Wv  = (const float*)d_in[8];
    const float* bv  = (const float*)d_in[9];
    float* out = (float*)d_out;

    float *pQ, *pK, *pV, *pPK, *pPQ;
    __nv_bfloat16 *pS2, *pS3;
    cudaGetSymbolAddress((void**)&pQ,  g_Q);
    cudaGetSymbolAddress((void**)&pK,  g_K);
    cudaGetSymbolAddress((void**)&pV,  g_V);
    cudaGetSymbolAddress((void**)&pPK, g_posK);
    cudaGetSymbolAddress((void**)&pPQ, g_posQ);
    cudaGetSymbolAddress((void**)&pS2, g_S2);
    cudaGetSymbolAddress((void**)&pS3, g_S3);

    static int attr_done = 0;
    if (!attr_done) {
        cudaFuncSetAttribute(pos_kernel,
            cudaFuncAttributeMaxDynamicSharedMemorySize, 2 * 128 * POS_STRIDE * 4);
        cudaFuncSetAttribute(attn_tc,
            cudaFuncAttributeMaxDynamicSharedMemorySize, ATTN_SMEM);
        attr_done = 1;
    }

    proj_all<<<dim3(4, 208), 256>>>(q, k, val, rel, Wq, bq, Wk, bk, Wv, bv,
                                    pQ, pK, pV, pPK, pPQ);
    pos_kernel<<<dim3(8, 8, 128), 256, 2 * 128 * POS_STRIDE * 4>>>(
        pQ, pK, pPK, pPQ, pS2, pS3);
    attn_tc<<<dim3(4, 64), 256, ATTN_SMEM>>>(pQ, pK, pV, pS2, pS3, out);
}

// round 16
// speedup vs baseline: 1.7642x; 1.7642x over previous
#include <cuda_runtime.h>
#include <cuda_bf16.h>
#include <math.h>
#include <stdint.h>

#define B_ 8
#define N_ 1024
#define C_ 512
#define H_ 8
#define D_ 64
#define S2_ 1024   // 2*SPAN

#define INV_SCALE 0.07216878364870323f   // 1/sqrt(64*3)

// ---------------- scratch (static device arrays; no allocation) -------------
__device__ float g_Q[(size_t)B_ * N_ * C_];
__device__ float g_K[(size_t)B_ * N_ * C_];
__device__ float g_V[(size_t)B_ * N_ * C_];
__device__ float g_posK[(size_t)S2_ * C_];
__device__ float g_posQ[(size_t)S2_ * C_];
__device__ __nv_bfloat16 g_S2[(size_t)B_ * H_ * N_ * S2_];   // prescaled, bf16
__device__ __nv_bfloat16 g_S3[(size_t)B_ * H_ * N_ * S2_];   // prescaled, bf16

// ---------------- tf32 mma helpers ------------------------------------------
__device__ __forceinline__ uint32_t f2tf32(float x) {
    uint32_t r;
    asm("cvt.rna.tf32.f32 %0, %1;" : "=r"(r) : "f"(x));
    return r;
}

__device__ __forceinline__ void mma_tf32(
    float c[4], uint32_t a0, uint32_t a1, uint32_t a2, uint32_t a3,
    uint32_t b0, uint32_t b1)
{
    asm volatile(
        "mma.sync.aligned.m16n8k8.row.col.f32.tf32.tf32.f32 "
        "{%0,%1,%2,%3}, {%4,%5,%6,%7}, {%8,%9}, {%0,%1,%2,%3};"
        : "+f"(c[0]), "+f"(c[1]), "+f"(c[2]), "+f"(c[3])
        : "r"(a0), "r"(a1), "r"(a2), "r"(a3), "r"(b0), "r"(b1));
}

// ============================================================================
// Merged projections (tf32 mma): Y[M,512] = X[M,512] @ W[512,512] + b
// ============================================================================
#define PA_STRIDE 36
#define PB_STRIDE 132
__global__ __launch_bounds__(256) void proj_all(
    const float* __restrict__ q, const float* __restrict__ k,
    const float* __restrict__ val, const float* __restrict__ rel,
    const float* __restrict__ Wq, const float* __restrict__ bq,
    const float* __restrict__ Wk, const float* __restrict__ bk,
    const float* __restrict__ Wv, const float* __restrict__ bv,
    float* __restrict__ pQ, float* __restrict__ pK, float* __restrict__ pV,
    float* __restrict__ pPK, float* __restrict__ pPQ)
{
    __shared__ uint32_t As[128][PA_STRIDE];
    __shared__ uint32_t Bs[32][PB_STRIDE];

    const int tid = threadIdx.x;
    const int warp = tid >> 5, lane = tid & 31;
    const int g = lane >> 2, t = lane & 3;
    const int wm = (warp & 1) << 6;
    const int wn = (warp >> 1) << 5;

    const int gy = blockIdx.y;
    const float *X, *W, *bias;
    float* Y;
    int mb;
    if (gy < 64)       { X = q;   W = Wq; bias = bq; Y = pQ;  mb = gy; }
    else if (gy < 128) { X = k;   W = Wk; bias = bk; Y = pK;  mb = gy - 64; }
    else if (gy < 192) { X = val; W = Wv; bias = bv; Y = pV;  mb = gy - 128; }
    else if (gy < 200) { X = rel; W = Wk; bias = bk; Y = pPK; mb = gy - 192; }
    else               { X = rel; W = Wq; bias = bq; Y = pPQ; mb = gy - 200; }

    const int m0 = mb << 7, n0 = blockIdx.x << 7;

    int arow[4], acol[4], brow[4], bcol[4];
#pragma unroll
    for (int i = 0; i < 4; i++) {
        int idx = (i << 8) + tid;
        arow[i] = idx >> 3;  acol[i] = (idx & 7) << 2;
        brow[i] = idx >> 5;  bcol[i] = (idx & 31) << 2;
    }

    float c[4][4][4];
#pragma unroll
    for (int mt = 0; mt < 4; mt++)
#pragma unroll
        for (int nt = 0; nt < 4; nt++)
#pragma unroll
            for (int e = 0; e < 4; e++) c[mt][nt][e] = 0.f;

    float4 xa[4], xb[4];
#pragma unroll
    for (int i = 0; i < 4; i++) {
        xa[i] = *(const float4*)&X[(size_t)(m0 + arow[i]) * 512 + acol[i]];
        xb[i] = *(const float4*)&W[(size_t)brow[i] * 512 + n0 + bcol[i]];
    }

    for (int k0 = 0; k0 < 512; k0 += 32) {
#pragma unroll
        for (int i = 0; i < 4; i++) {
            *(uint4*)&As[arow[i]][acol[i]] = make_uint4(
                f2tf32(xa[i].x), f2tf32(xa[i].y), f2tf32(xa[i].z), f2tf32(xa[i].w));
            *(uint4*)&Bs[brow[i]][bcol[i]] = make_uint4(
                f2tf32(xb[i].x), f2tf32(xb[i].y), f2tf32(xb[i].z), f2tf32(xb[i].w));
        }
        __syncthreads();

        if (k0 + 32 < 512) {
#pragma unroll
            for (int i = 0; i < 4; i++) {
                xa[i] = *(const float4*)&X[(size_t)(m0 + arow[i]) * 512 + k0 + 32 + acol[i]];
                xb[i] = *(const float4*)&W[(size_t)(k0 + 32 + brow[i]) * 512 + n0 + bcol[i]];
            }
        }

#pragma unroll
        for (int k8 = 0; k8 < 32; k8 += 8) {
            uint32_t a[4][4], b[4][2];
#pragma unroll
            for (int mt = 0; mt < 4; mt++) {
                int rb = wm + (mt << 4);
                a[mt][0] = As[rb + g][k8 + t];
                a[mt][1] = As[rb + g + 8][k8 + t];
                a[mt][2] = As[rb + g][k8 + t + 4];
                a[mt][3] = As[rb + g + 8][k8 + t + 4];
            }
#pragma unroll
            for (int nt = 0; nt < 4; nt++) {
                int nb = wn + (nt << 3) + g;
                b[nt][0] = Bs[k8 + t][nb];
                b[nt][1] = Bs[k8 + t + 4][nb];
            }
#pragma unroll
            for (int mt = 0; mt < 4; mt++)
#pragma unroll
                for (int nt = 0; nt < 4; nt++)
                    mma_tf32(c[mt][nt], a[mt][0], a[mt][1], a[mt][2], a[mt][3],
                             b[nt][0], b[nt][1]);
        }
        __syncthreads();
    }

#pragma unroll
    for (int mt = 0; mt < 4; mt++) {
        int r0 = m0 + wm + (mt << 4) + g;
#pragma unroll
        for (int nt = 0; nt < 4; nt++) {
            int cb = n0 + wn + (nt << 3) + (t << 1);
            float b0v = bias[cb], b1v = bias[cb + 1];
            *(float2*)&Y[(size_t)r0 * 512 + cb] =
                make_float2(c[mt][nt][0] + b0v, c[mt][nt][1] + b1v);
            *(float2*)&Y[(size_t)(r0 + 8) * 512 + cb] =
                make_float2(c[mt][nt][2] + b0v, c[mt][nt][3] + b1v);
        }
    }
}

// ============================================================================
// S2/S3 (tf32 mma), banded, bf16 output (prescaled).
// __launch_bounds__(256, 2): guarantee 2 CTAs/SM to overlap one CTA's tile
// load with the other's mma burst (regs already at the 128 target).
// ============================================================================
#define POS_STRIDE 68
__global__ __launch_bounds__(256, 2) void pos_kernel(
    const float* __restrict__ Q, const float* __restrict__ K,
    const float* __restrict__ posK, const float* __restrict__ posQ,
    __nv_bfloat16* __restrict__ S2, __nv_bfloat16* __restrict__ S3)
{
    const int by = blockIdx.y, bx = blockIdx.x;
    const int z = blockIdx.z;
    const bool isS3 = z >= 64;
    if (!isS3) {
        if (bx > by + 4 || by > bx + 4) return;
    } else {
        int s = bx + by;
        if (s < 3 || s > 11) return;
    }

    extern __shared__ uint32_t psm[];
    uint32_t (*As)[POS_STRIDE] = (uint32_t(*)[POS_STRIDE])psm;
    uint32_t (*Ps)[POS_STRIDE] = (uint32_t(*)[POS_STRIDE])(psm + 128 * POS_STRIDE);

    const int zz = isS3 ? z - 64 : z;
    const int b = zz >> 3, h = zz & 7;
    const int m0 = by << 7, n0 = bx << 7;
    const int tid = threadIdx.x;
    const int warp = tid >> 5, lane = tid & 31;
    const int g = lane >> 2, t = lane & 3;
    const int wm = (warp & 1) << 6;
    const int wn = (warp >> 1) << 5;

    const float* A = (isS3 ? K : Q) + ((size_t)(b * N_ + m0)) * C_ + h * D_;
    const float* P = (isS3 ? posQ : posK) + (size_t)n0 * C_ + h * D_;
    __nv_bfloat16* OUT = (isS3 ? S3 : S2) + (size_t)zz * N_ * S2_;

#pragma unroll
    for (int i = 0; i < 8; i++) {
        int idx = (i << 8) + tid;
        int row = idx >> 4, cc = (idx & 15) << 2;
        float4 va = *(const float4*)&A[(size_t)row * C_ + cc];
        *(uint4*)&As[row][cc] = make_uint4(f2tf32(va.x), f2tf32(va.y),
                                           f2tf32(va.z), f2tf32(va.w));
        float4 vp = *(const float4*)&P[(size_t)row * C_ + cc];
        *(uint4*)&Ps[row][cc] = make_uint4(f2tf32(vp.x), f2tf32(vp.y),
                                           f2tf32(vp.z), f2tf32(vp.w));
    }
    __syncthreads();

    float c[4][4][4];
#pragma unroll
    for (int mt = 0; mt < 4; mt++)
#pragma unroll
        for (int nt = 0; nt < 4; nt++)
#pragma unroll
            for (int e = 0; e < 4; e++) c[mt][nt][e] = 0.f;

#pragma unroll
    for (int k8 = 0; k8 < 64; k8 += 8) {
        uint32_t a[4][4], bfr[4][2];
#pragma unroll
        for (int mt = 0; mt < 4; mt++) {
            int rb = wm + (mt << 4);
            a[mt][0] = As[rb + g][k8 + t];
            a[mt][1] = As[rb + g + 8][k8 + t];
            a[mt][2] = As[rb + g][k8 + t + 4];
            a[mt][3] = As[rb + g + 8][k8 + t + 4];
        }
#pragma unroll
        for (int nt = 0; nt < 4; nt++) {
            int nb = wn + (nt << 3) + g;
            bfr[nt][0] = Ps[nb][k8 + t];
            bfr[nt][1] = Ps[nb][k8 + t + 4];
        }
#pragma unroll
        for (int mt = 0; mt < 4; mt++)
#pragma unroll
            for (int nt = 0; nt < 4; nt++)
                mma_tf32(c[mt][nt], a[mt][0], a[mt][1], a[mt][2], a[mt][3],
                         bfr[nt][0], bfr[nt][1]);
    }

#pragma unroll
    for (int mt = 0; mt < 4; mt++) {
        int r0 = m0 + wm + (mt << 4) + g;
#pragma unroll
        for (int nt = 0; nt < 4; nt++) {
            int cb = n0 + wn + (nt << 3) + (t << 1);
            *(__nv_bfloat162*)&OUT[(size_t)r0 * S2_ + cb] =
                __floats2bfloat162_rn(c[mt][nt][0] * INV_SCALE,
                                      c[mt][nt][1] * INV_SCALE);
            *(__nv_bfloat162*)&OUT[(size_t)(r0 + 8) * S2_ + cb] =
                __floats2bfloat162_rn(c[mt][nt][2] * INV_SCALE,
                                      c[mt][nt][3] * INV_SCALE);
        }
    }
}

// ============================================================================
// Tensor-core fused attention — round-14 structure (256-row CTA, 8 warps,
// 32-row warp tiles, scalar fragment loads). Best-known attn config.
// ============================================================================
#define AQ_STR 68
#define AV_STR 72
#define ATTN_SMEM ((256*AQ_STR + 64*AQ_STR + 64*AV_STR + 256*AQ_STR) * 4)
__global__ __launch_bounds__(256) void attn_tc(
    const float* __restrict__ Q, const float* __restrict__ K,
    const float* __restrict__ V, const __nv_bfloat16* __restrict__ S2,
    const __nv_bfloat16* __restrict__ S3, float* __restrict__ OUT)
{
    extern __shared__ uint32_t asmem[];
    uint32_t (*Qs)[AQ_STR] = (uint32_t(*)[AQ_STR])asmem;                      // [256][68]
    uint32_t (*Ks)[AQ_STR] = (uint32_t(*)[AQ_STR])(asmem + 256 * AQ_STR);     // [64][68]
    uint32_t (*Vs)[AV_STR] = (uint32_t(*)[AV_STR])(asmem + 320 * AQ_STR);     // [64][72]
    uint32_t (*Ps)[AQ_STR] = (uint32_t(*)[AQ_STR])(asmem + 320 * AQ_STR + 64 * AV_STR); // [256][68]

    const int z = blockIdx.y, b = z >> 3, h = z & 7;
    const int q0 = blockIdx.x << 8;           // 256-row q tile
    const int tid = threadIdx.x;
    const int warp = tid >> 5, lane = tid & 31;
    const int g = lane >> 2, t = lane & 3;

    // Load Q tile (256x64), prescale, tf32 into Qs
#pragma unroll
    for (int i = 0; i < 16; i++) {
        int idx = (i << 8) + tid;
        int row = idx >> 4, cc = (idx & 15) << 2;
        float4 v = *(const float4*)&Q[((size_t)(b * N_ + q0 + row)) * C_ + h * D_ + cc];
        *(uint4*)&Qs[row][cc] = make_uint4(
            f2tf32(v.x * INV_SCALE), f2tf32(v.y * INV_SCALE),
            f2tf32(v.z * INV_SCALE), f2tf32(v.w * INV_SCALE));
    }

    const int qrl = (warp << 5) + g;          // local q row of fragment 0
    const int qg0 = q0 + qrl;                 // rows qg0, +8, +16, +24
    const __nv_bfloat16* s2r0 = S2 + ((size_t)z * N_ + qg0) * S2_;
    const __nv_bfloat16* s2r1 = s2r0 + (size_t)8  * S2_;
    const __nv_bfloat16* s2r2 = s2r0 + (size_t)16 * S2_;
    const __nv_bfloat16* s2r3 = s2r0 + (size_t)24 * S2_;
    const __nv_bfloat16* S3z = S3 + (size_t)z * N_ * S2_;

    float o[2][8][4];
#pragma unroll
    for (int mf = 0; mf < 2; mf++)
#pragma unroll
        for (int nt = 0; nt < 8; nt++)
#pragma unroll
            for (int e = 0; e < 4; e++) o[mf][nt][e] = 0.f;
    float mr[4] = {-1e30f, -1e30f, -1e30f, -1e30f};
    float lr[4] = {0.f, 0.f, 0.f, 0.f};

    for (int k0 = 0; k0 < N_; k0 += 64) {
        // ---- load K,V tiles (64x64 each), 4 float4 per thread ----
#pragma unroll
        for (int i = 0; i < 4; i++) {
            int idx = (i << 8) + tid;
            int row = idx >> 4, cc = (idx & 15) << 2;
            float4 kv = *(const float4*)&K[((size_t)(b * N_ + k0 + row)) * C_ + h * D_ + cc];
            *(uint4*)&Ks[row][cc] = make_uint4(f2tf32(kv.x), f2tf32(kv.y),
                                               f2tf32(kv.z), f2tf32(kv.w));
            float4 vv = *(const float4*)&V[((size_t)(b * N_ + k0 + row)) * C_ + h * D_ + cc];
            *(uint4*)&Vs[row][cc] = make_uint4(f2tf32(vv.x), f2tf32(vv.y),
                                               f2tf32(vv.z), f2tf32(vv.w));
        }
        __syncthreads();

        // ---- QK: warp computes 32 x 64 scores (2 m16 fragments) ----
        float cf[2][8][4];
#pragma unroll
        for (int mf = 0; mf < 2; mf++)
#pragma unroll
            for (int nt = 0; nt < 8; nt++)
#pragma unroll
                for (int e = 0; e < 4; e++) cf[mf][nt][e] = 0.f;
#pragma unroll
        for (int k8 = 0; k8 < 64; k8 += 8) {
            uint32_t a00 = Qs[qrl][k8 + t];
            uint32_t a01 = Qs[qrl + 8][k8 + t];
            uint32_t a02 = Qs[qrl][k8 + t + 4];
            uint32_t a03 = Qs[qrl + 8][k8 + t + 4];
            uint32_t a10 = Qs[qrl + 16][k8 + t];
            uint32_t a11 = Qs[qrl + 24][k8 + t];
            uint32_t a12 = Qs[qrl + 16][k8 + t + 4];
            uint32_t a13 = Qs[qrl + 24][k8 + t + 4];
#pragma unroll
            for (int nt = 0; nt < 8; nt++) {
                uint32_t b0 = Ks[(nt << 3) + g][k8 + t];
                uint32_t b1 = Ks[(nt << 3) + g][k8 + t + 4];
                mma_tf32(cf[0][nt], a00, a01, a02, a03, b0, b1);
                mma_tf32(cf[1][nt], a10, a11, a12, a13, b0, b1);
            }
        }

        // ---- add position terms (bf16 gathers, index clip(q-k+512)) ----
#pragma unroll
        for (int nt = 0; nt < 8; nt++) {
            int kj = k0 + (nt << 3) + (t << 1);
            const __nv_bfloat16* s3c0 = S3z + (size_t)kj * S2_;
            const __nv_bfloat16* s3c1 = s3c0 + S2_;
            int d00 = qg0 - kj + 512;
            int c00 = min(max(d00, 0), 1023);
            int c01 = min(max(d00 - 1, 0), 1023);
            int c10 = min(max(d00 + 8, 0), 1023);
            int c11 = min(max(d00 + 7, 0), 1023);
            int c20 = min(max(d00 + 16, 0), 1023);
            int c21 = min(max(d00 + 15, 0), 1023);
            int c30 = min(max(d00 + 24, 0), 1023);
            int c31 = min(max(d00 + 23, 0), 1023);
            cf[0][nt][0] += __bfloat162float(s2r0[c00]) + __bfloat162float(s3c0[c00]);
            cf[0][nt][1] += __bfloat162float(s2r0[c01]) + __bfloat162float(s3c1[c01]);
            cf[0][nt][2] += __bfloat162float(s2r1[c10]) + __bfloat162float(s3c0[c10]);
            cf[0][nt][3] += __bfloat162float(s2r1[c11]) + __bfloat162float(s3c1[c11]);
            cf[1][nt][0] += __bfloat162float(s2r2[c20]) + __bfloat162float(s3c0[c20]);
            cf[1][nt][1] += __bfloat162float(s2r2[c21]) + __bfloat162float(s3c1[c21]);
            cf[1][nt][2] += __bfloat162float(s2r3[c30]) + __bfloat162float(s3c0[c30]);
            cf[1][nt][3] += __bfloat162float(s2r3[c31]) + __bfloat162float(s3c1[c31]);
        }

        // ---- online softmax for 4 owned rows (quad reduce over t) ----
        float tm[4] = {-1e30f, -1e30f, -1e30f, -1e30f};
#pragma unroll
        for (int nt = 0; nt < 8; nt++) {
            tm[0] = fmaxf(tm[0], fmaxf(cf[0][nt][0], cf[0][nt][1]));
            tm[1] = fmaxf(tm[1], fmaxf(cf[0][nt][2], cf[0][nt][3]));
            tm[2] = fmaxf(tm[2], fmaxf(cf[1][nt][0], cf[1][nt][1]));
            tm[3] = fmaxf(tm[3], fmaxf(cf[1][nt][2], cf[1][nt][3]));
        }
        float al[4];
#pragma unroll
        for (int r = 0; r < 4; r++) {
            tm[r] = fmaxf(tm[r], __shfl_xor_sync(0xffffffffu, tm[r], 1));
            tm[r] = fmaxf(tm[r], __shfl_xor_sync(0xffffffffu, tm[r], 2));
            float nm = fmaxf(mr[r], tm[r]);
            al[r] = __expf(mr[r] - nm);
            mr[r] = nm;
        }

        float rs[4] = {0.f, 0.f, 0.f, 0.f};
#pragma unroll
        for (int nt = 0; nt < 8; nt++) {
            cf[0][nt][0] = __expf(cf[0][nt][0] - mr[0]); rs[0] += cf[0][nt][0];
            cf[0][nt][1] = __expf(cf[0][nt][1] - mr[0]); rs[0] += cf[0][nt][1];
            cf[0][nt][2] = __expf(cf[0][nt][2] - mr[1]); rs[1] += cf[0][nt][2];
            cf[0][nt][3] = __expf(cf[0][nt][3] - mr[1]); rs[1] += cf[0][nt][3];
            cf[1][nt][0] = __expf(cf[1][nt][0] - mr[2]); rs[2] += cf[1][nt][0];
            cf[1][nt][1] = __expf(cf[1][nt][1] - mr[2]); rs[2] += cf[1][nt][1];
            cf[1][nt][2] = __expf(cf[1][nt][2] - mr[3]); rs[3] += cf[1][nt][2];
            cf[1][nt][3] = __expf(cf[1][nt][3] - mr[3]); rs[3] += cf[1][nt][3];
        }
#pragma unroll
        for (int r = 0; r < 4; r++) {
            rs[r] += __shfl_xor_sync(0xffffffffu, rs[r], 1);
            rs[r] += __shfl_xor_sync(0xffffffffu, rs[r], 2);
            lr[r] = lr[r] * al[r] + rs[r];
        }
#pragma unroll
        for (int nt = 0; nt < 8; nt++) {
            o[0][nt][0] *= al[0]; o[0][nt][1] *= al[0];
            o[0][nt][2] *= al[1]; o[0][nt][3] *= al[1];
            o[1][nt][0] *= al[2]; o[1][nt][1] *= al[2];
            o[1][nt][2] *= al[3]; o[1][nt][3] *= al[3];
        }

        // ---- P -> smem (tf32); warp-local rows, warp-sync only ----
#pragma unroll
        for (int nt = 0; nt < 8; nt++) {
            int col = (nt << 3) + (t << 1);
            *(uint2*)&Ps[qrl][col]      = make_uint2(f2tf32(cf[0][nt][0]), f2tf32(cf[0][nt][1]));
            *(uint2*)&Ps[qrl + 8][col]  = make_uint2(f2tf32(cf[0][nt][2]), f2tf32(cf[0][nt][3]));
            *(uint2*)&Ps[qrl + 16][col] = make_uint2(f2tf32(cf[1][nt][0]), f2tf32(cf[1][nt][1]));
            *(uint2*)&Ps[qrl + 24][col] = make_uint2(f2tf32(cf[1][nt][2]), f2tf32(cf[1][nt][3]));
        }
        __syncwarp();

        // ---- o += P · V ----
#pragma unroll
        for (int k8 = 0; k8 < 64; k8 += 8) {
            uint32_t a00 = Ps[qrl][k8 + t];
            uint32_t a01 = Ps[qrl + 8][k8 + t];
            uint32_t a02 = Ps[qrl][k8 + t + 4];
            uint32_t a03 = Ps[qrl + 8][k8 + t + 4];
            uint32_t a10 = Ps[qrl + 16][k8 + t];
            uint32_t a11 = Ps[qrl + 24][k8 + t];
            uint32_t a12 = Ps[qrl + 16][k8 + t + 4];
            uint32_t a13 = Ps[qrl + 24][k8 + t + 4];
#pragma unroll
            for (int nt = 0; nt < 8; nt++) {
                uint32_t b0 = Vs[k8 + t][(nt << 3) + g];
                uint32_t b1 = Vs[k8 + t + 4][(nt << 3) + g];
                mma_tf32(o[0][nt], a00, a01, a02, a03, b0, b1);
                mma_tf32(o[1][nt], a10, a11, a12, a13, b0, b1);
            }
        }
        __syncthreads();   // Ks/Vs consumed; next iteration overwrites
    }

    // ---- epilogue: 4 owned rows ----
    float inv[4];
#pragma unroll
    for (int r = 0; r < 4; r++) inv[r] = 1.f / lr[r];
#pragma unroll
    for (int nt = 0; nt < 8; nt++) {
        int col = h * D_ + (nt << 3) + (t << 1);
        *(float2*)&OUT[((size_t)(b * N_ + qg0)) * C_ + col] =
            make_float2(o[0][nt][0] * inv[0], o[0][nt][1] * inv[0]);
        *(float2*)&OUT[((size_t)(b * N_ + qg0 + 8)) * C_ + col] =
            make_float2(o[0][nt][2] * inv[1], o[0][nt][3] * inv[1]);
        *(float2*)&OUT[((size_t)(b * N_ + qg0 + 16)) * C_ + col] =
            make_float2(o[1][nt][0] * inv[2], o[1][nt][1] * inv[2]);
        *(float2*)&OUT[((size_t)(b * N_ + qg0 + 24)) * C_ + col] =
            make_float2(o[1][nt][2] * inv[3], o[1][nt][3] * inv[3]);
    }
}

// ---------------------------------------------------------------------------
extern "C" void kernel_launch(void* const* d_in, const int* in_sizes, int n_in,
                              void* d_out, int out_size)
{
    const float* q   = (const float*)d_in[0];
    const float* k   = (const float*)d_in[1];
    const float* val = (const float*)d_in[2];
    const float* rel = (const float*)d_in[3];
    const float* Wq  = (const float*)d_in[4];
    const float* bq  = (const float*)d_in[5];
    const float* Wk  = (const float*)d_in[6];
    const float* bk  = (const float*)d_in[7];
    const float* Wv  = (const float*)d_in[8];
    const float* bv  = (const float*)d_in[9];
    float* out = (float*)d_out;

    float *pQ, *pK, *pV, *pPK, *pPQ;
    __nv_bfloat16 *pS2, *pS3;
    cudaGetSymbolAddress((void**)&pQ,  g_Q);
    cudaGetSymbolAddress((void**)&pK,  g_K);
    cudaGetSymbolAddress((void**)&pV,  g_V);
    cudaGetSymbolAddress((void**)&pPK, g_posK);
    cudaGetSymbolAddress((void**)&pPQ, g_posQ);
    cudaGetSymbolAddress((void**)&pS2, g_S2);
    cudaGetSymbolAddress((void**)&pS3, g_S3);

    static int attr_done = 0;
    if (!attr_done) {
        cudaFuncSetAttribute(pos_kernel,
            cudaFuncAttributeMaxDynamicSharedMemorySize, 2 * 128 * POS_STRIDE * 4);
        cudaFuncSetAttribute(attn_tc,
            cudaFuncAttributeMaxDynamicSharedMemorySize, ATTN_SMEM);
        attr_done = 1;
    }

    proj_all<<<dim3(4, 208), 256>>>(q, k, val, rel, Wq, bq, Wk, bk, Wv, bv,
                                    pQ, pK, pV, pPK, pPQ);
    pos_kernel<<<dim3(8, 8, 128), 256, 2 * 128 * POS_STRIDE * 4>>>(
        pQ, pK, pPK, pPQ, pS2, pS3);
    attn_tc<<<dim3(4, 64), 256, ATTN_SMEM>>>(pQ, pK, pV, pS2, pS3, out);
}